// round 15
// baseline (speedup 1.0000x reference)
#include <cuda_runtime.h>
#include <cuda_fp16.h>
#include <cstdint>
#include <cstddef>

// ---------------- problem constants ----------------
#define BDIM   4096
#define INDIM  2048
#define OUTDIM 2048
#define NCOEFF 8
#define KTOT   18432              // INDIM + INDIM*NCOEFF
#define NKT    288                // KTOT / 64

// ---------------- GEMM tiling (R14-proven geometry) ----------------
#define BM 256
#define BN 256
#define BK 64                     // 64 fp16 = 128 B = one SW128 row
#define NSTG 3
#define STG_BYTES   65536         // A 32K (256 rows) + W 32K (256 rows)
#define STG_B_OFF   32768
#define SMEM_BYTES  (2048 + NSTG * STG_BYTES)   // 198656

// ---------------- device scratch (static globals; no runtime alloc) ----------------
__device__ __align__(128) __half g_A[(size_t)BDIM * KTOT];
__device__ __align__(128) __half g_W[(size_t)OUTDIM * KTOT];

// ---------------- arch-feature detection (R10/R13/R14-proven) ----------------
#if defined(__CUDA_ARCH_FEAT_SM103_ALL) || defined(__CUDA_ARCH_FEAT_SM100_ALL) || \
    (defined(__CUDA_ARCH_SPECIFIC__) && defined(__CUDA_ARCH__) && __CUDA_ARCH__ >= 1000)
#define HAS_TC 1
#else
#define HAS_TC 0
#endif

// ---------------- common PTX helpers (baseline-PTX safe) ----------------
__device__ __forceinline__ uint32_t smem_u32(const void* p) {
    uint32_t a;
    asm("{ .reg .u64 t; cvta.to.shared.u64 t, %1; cvt.u32.u64 %0, t; }" : "=r"(a) : "l"(p));
    return a;
}
__device__ __forceinline__ void cp_async16(uint32_t dst, const void* src) {
    asm volatile("cp.async.cg.shared.global [%0], [%1], 16;" :: "r"(dst), "l"(src) : "memory");
}

// ---------------- prep: weights -> fp16 [OUT, KTOT] ----------------
__global__ void wprep_kernel(const float* __restrict__ bw, const float* __restrict__ sw) {
    size_t e = ((size_t)blockIdx.x * blockDim.x + threadIdx.x) * 4;
    if (e >= (size_t)OUTDIM * KTOT) return;
    size_t o = e / KTOT;
    size_t k = e - o * KTOT;
    float4 v;
    if (k < INDIM) {
        v = *(const float4*)(bw + o * INDIM + k);
    } else {
        v = *(const float4*)(sw + o * (size_t)(INDIM * NCOEFF) + (k - INDIM));
        v.x = rintf(v.x * 32.f) * 0.03125f;
        v.y = rintf(v.y * 32.f) * 0.03125f;
        v.z = rintf(v.z * 32.f) * 0.03125f;
        v.w = rintf(v.w * 32.f) * 0.03125f;
    }
    __half h[4];
    h[0] = __float2half_rn(v.x); h[1] = __float2half_rn(v.y);
    h[2] = __float2half_rn(v.z); h[3] = __float2half_rn(v.w);
    *(uint2*)(g_W + e) = *(const uint2*)h;
}

// ---------------- prep: x + cubic b-spline basis -> fp16 plane ----------------
__global__ void aprep_kernel(const float* __restrict__ x, const float* __restrict__ grid) {
    int idx = blockIdx.x * blockDim.x + threadIdx.x;
    if (idx >= BDIM * INDIM) return;
    int b = idx / INDIM;
    int i = idx - b * INDIM;
    float xv = x[idx];
    float g[12];
#pragma unroll
    for (int j = 0; j < 12; ++j) g[j] = grid[i * 12 + j];

    float b0[11];
#pragma unroll
    for (int j = 0; j < 11; ++j) b0[j] = (xv >= g[j] && xv < g[j + 1]) ? 1.f : 0.f;
    float b1[10];
#pragma unroll
    for (int j = 0; j < 10; ++j)
        b1[j] = (xv - g[j]) / (g[j + 1] - g[j] + 1e-8f) * b0[j]
              + (g[j + 2] - xv) / (g[j + 2] - g[j + 1] + 1e-8f) * b0[j + 1];
    float b2[9];
#pragma unroll
    for (int j = 0; j < 9; ++j)
        b2[j] = (xv - g[j]) / (g[j + 2] - g[j] + 1e-8f) * b1[j]
              + (g[j + 3] - xv) / (g[j + 3] - g[j + 1] + 1e-8f) * b1[j + 1];
    float b3[8];
#pragma unroll
    for (int j = 0; j < 8; ++j)
        b3[j] = (xv - g[j]) / (g[j + 3] - g[j] + 1e-8f) * b2[j]
              + (g[j + 4] - xv) / (g[j + 4] - g[j + 1] + 1e-8f) * b2[j + 1];

    size_t rowoff = (size_t)b * KTOT;
    g_A[rowoff + i] = __float2half_rn(xv);

    __half h[8];
#pragma unroll
    for (int c = 0; c < 8; ++c) h[c] = __float2half_rn(b3[c]);
    *(uint4*)(g_A + rowoff + INDIM + (size_t)i * 8) = *(const uint4*)h;
}

// ---------------- stage loader: A 256x128B + W 256x128B, SW128 swizzled ----------------
__device__ __forceinline__ void load_stage(int kt, int m0, int o0, uint32_t stg, int tid) {
    size_t kcol = (size_t)kt * BK;
#pragma unroll
    for (int it = 0; it < 8; ++it) {          // 2048 16B-chunks per operand
        int idx = tid + it * 256;
        int r = idx >> 3, c = idx & 7;        // r in 0..255
        uint32_t off = (uint32_t)(r * 128 + c * 16);
        uint32_t sw = off ^ ((off >> 3) & 0x70);
        cp_async16(stg + sw, g_A + (size_t)(m0 + r) * KTOT + kcol + (size_t)c * 8);
        cp_async16(stg + STG_B_OFF + sw,
                   g_W + (size_t)(o0 + r) * KTOT + kcol + (size_t)c * 8);
    }
}

#if HAS_TC
// ================= tcgen05 path helpers (R13/R14-validated) =================
__device__ __forceinline__ uint32_t elect1() {
    uint32_t r;
    asm volatile("{ .reg .pred p; elect.sync _|p, 0xFFFFFFFF; selp.b32 %0, 1, 0, p; }" : "=r"(r));
    return r;
}
__device__ __forceinline__ void mbar_init(uint32_t a, uint32_t cnt) {
    asm volatile("mbarrier.init.shared.b64 [%0], %1;" :: "r"(a), "r"(cnt) : "memory");
}
__device__ __forceinline__ void mbar_wait(uint32_t a, uint32_t parity) {
    asm volatile(
        "{\n\t.reg .pred P1;\n\t"
        "W_%=:\n\t"
        "mbarrier.try_wait.parity.acquire.cta.shared::cta.b64 P1, [%0], %1, 0x989680;\n\t"
        "@P1 bra.uni D_%=;\n\t"
        "bra.uni W_%=;\n\t"
        "D_%=:\n\t}"
        :: "r"(a), "r"(parity) : "memory");
}
__device__ __forceinline__ void cp_mbar_arrive(uint32_t a) {
    asm volatile("cp.async.mbarrier.arrive.noinc.shared.b64 [%0];" :: "r"(a) : "memory");
}
__device__ __forceinline__ uint64_t mk_desc(uint32_t addr) {
    return ((uint64_t)2 << 61) | ((uint64_t)1 << 46) | ((uint64_t)64 << 32)
         | ((uint64_t)1 << 16) | ((uint64_t)(addr >> 4) & 0x3FFF);
}
#define IDESC 0x08200010u   // F32 accum, f16 x f16, N=128, M=128 (proven)
__device__ __forceinline__ void mma_f16_ss(uint32_t d, uint64_t a, uint64_t b, uint32_t en) {
    asm volatile(
        "{\n\t.reg .pred p;\n\tsetp.ne.u32 p, %4, 0;\n\t"
        "tcgen05.mma.cta_group::1.kind::f16 [%0], %1, %2, %3, {%5,%5,%5,%5}, p;\n\t}"
        :: "r"(d), "l"(a), "l"(b), "r"(IDESC), "r"(en), "r"(0u) : "memory");
}
__device__ __forceinline__ void tmem_ld32(uint32_t* r, uint32_t addr) {
    asm volatile(
        "tcgen05.ld.sync.aligned.32x32b.x32.b32 "
        "{%0, %1, %2, %3, %4, %5, %6, %7, "
        " %8, %9, %10, %11, %12, %13, %14, %15, "
        " %16, %17, %18, %19, %20, %21, %22, %23, "
        " %24, %25, %26, %27, %28, %29, %30, %31}, [%32];"
        : "=r"(r[0]),  "=r"(r[1]),  "=r"(r[2]),  "=r"(r[3]),
          "=r"(r[4]),  "=r"(r[5]),  "=r"(r[6]),  "=r"(r[7]),
          "=r"(r[8]),  "=r"(r[9]),  "=r"(r[10]), "=r"(r[11]),
          "=r"(r[12]), "=r"(r[13]), "=r"(r[14]), "=r"(r[15]),
          "=r"(r[16]), "=r"(r[17]), "=r"(r[18]), "=r"(r[19]),
          "=r"(r[20]), "=r"(r[21]), "=r"(r[22]), "=r"(r[23]),
          "=r"(r[24]), "=r"(r[25]), "=r"(r[26]), "=r"(r[27]),
          "=r"(r[28]), "=r"(r[29]), "=r"(r[30]), "=r"(r[31])
        : "r"(addr));
}

// issue the 16 MMAs for one k-tile stage
__device__ __forceinline__ void issue_tile(uint32_t tmem, uint32_t stg, int first) {
    asm volatile("fence.proxy.async.shared::cta;" ::: "memory");
    uint64_t da0 = mk_desc(stg);
    uint64_t da1 = mk_desc(stg + 16384);                 // A rows 128..255
    uint64_t db0 = mk_desc(stg + STG_B_OFF);
    uint64_t db1 = mk_desc(stg + STG_B_OFF + 16384);     // W rows 128..255
#pragma unroll
    for (int ks = 0; ks < 4; ++ks) {
        uint64_t d = (uint64_t)(ks * 2);
        uint32_t en = (first && ks == 0) ? 0u : 1u;
        mma_f16_ss(tmem +   0, da0 + d, db0 + d, en);
        mma_f16_ss(tmem + 128, da0 + d, db1 + d, en);
        mma_f16_ss(tmem + 256, da1 + d, db0 + d, en);
        mma_f16_ss(tmem + 384, da1 + d, db1 + d, en);
    }
}
#endif

// ---------------- GEMM: C[4096,2048] = A @ W^T, fp32 accum ----------------
__global__ void __launch_bounds__(256, 1)
gemm_kernel(float* __restrict__ out) {
    extern __shared__ char smem[];
    uint32_t sb = smem_u32(smem);
    uint32_t tiles = (sb + 128 + 1023) & ~1023u;
    int tid = threadIdx.x;
    int wid = tid >> 5;
    int lane = tid & 31;
    int m0 = blockIdx.y * BM;
    int o0 = blockIdx.x * BN;

#if HAS_TC
    // ctrl layout: [sb+0] tmem ptr; full[s] at sb+8+8s; mmad[s] at sb+40+8s
    uint32_t FULL = sb + 8, MMAD = sb + 40;
    if (wid == 0)
        asm volatile("tcgen05.alloc.cta_group::1.sync.aligned.shared::cta.b32 [%0], %1;"
                     :: "r"(sb), "r"(512u) : "memory");
    if (tid == 0) {
#pragma unroll
        for (int s = 0; s < NSTG; ++s) {
            mbar_init(FULL + 8u * s, 256);
            mbar_init(MMAD + 8u * s, 1);
        }
    }
    __syncthreads();
    uint32_t tmem;
    asm volatile("ld.shared.b32 %0, [%1];" : "=r"(tmem) : "r"(sb));

    uint32_t fph0 = 0, fph1 = 0, fph2 = 0;   // full phases (issuer)
    uint32_t mph0 = 0, mph1 = 0, mph2 = 0;   // mmad phases (per thread)

    for (int kt = 0; kt < NKT; ++kt) {
        int s = kt % NSTG;
        // slot-reuse gate: MMAs of tile kt-3 (same slot) must be committed
        if (kt >= NSTG) {
            if (s == 0)      { mbar_wait(MMAD,      mph0); mph0 ^= 1; }
            else if (s == 1) { mbar_wait(MMAD + 8,  mph1); mph1 ^= 1; }
            else             { mbar_wait(MMAD + 16, mph2); mph2 ^= 1; }
        }
        load_stage(kt, m0, o0, tiles + (uint32_t)s * STG_BYTES, tid);
        cp_mbar_arrive(FULL + 8u * s);

        // elected thread trails by 2 tiles issuing MMAs
        if (wid == 0 && elect1() && kt >= 2) {
            int t = kt - 2, ts = t % NSTG;
            if (ts == 0)      { mbar_wait(FULL,      fph0); fph0 ^= 1; }
            else if (ts == 1) { mbar_wait(FULL + 8,  fph1); fph1 ^= 1; }
            else              { mbar_wait(FULL + 16, fph2); fph2 ^= 1; }
            issue_tile(tmem, tiles + (uint32_t)ts * STG_BYTES, t == 0);
            asm volatile(
                "tcgen05.commit.cta_group::1.mbarrier::arrive::one.shared::cluster.b64 [%0];"
                :: "r"(MMAD + 8u * ts) : "memory");
        }
    }
    // tail: tiles NKT-2, NKT-1
    if (wid == 0 && elect1()) {
#pragma unroll
        for (int t = NKT - 2; t < NKT; ++t) {
            int ts = t % NSTG;
            if (ts == 0)      { mbar_wait(FULL,      fph0); fph0 ^= 1; }
            else if (ts == 1) { mbar_wait(FULL + 8,  fph1); fph1 ^= 1; }
            else              { mbar_wait(FULL + 16, fph2); fph2 ^= 1; }
            issue_tile(tmem, tiles + (uint32_t)ts * STG_BYTES, 0);
            asm volatile(
                "tcgen05.commit.cta_group::1.mbarrier::arrive::one.shared::cluster.b64 [%0];"
                :: "r"(MMAD + 8u * ts) : "memory");
        }
    }
    // all threads: wait final commit (slot (NKT-1)%3 = 2)
    mbar_wait(MMAD + 16, mph2);
    asm volatile("tcgen05.fence::after_thread_sync;" ::: "memory");

    // epilogue: warp w -> m-half h=w>>2 (TMEM cols h*256..+255), rows (w&3)*32+lane
    {
        int sub = wid & 3;
        int h = wid >> 2;
        float* orow = out + (size_t)(m0 + h * 128 + sub * 32 + lane) * OUTDIM + o0;
        uint32_t cbase = tmem + (uint32_t)(h * 256);
#pragma unroll
        for (int ch = 0; ch < 8; ++ch) {
            uint32_t r[32];
            tmem_ld32(r, cbase + (uint32_t)(ch * 32));
            asm volatile("tcgen05.wait::ld.sync.aligned;" ::: "memory");
#pragma unroll
            for (int q = 0; q < 8; ++q) {
                float4 v;
                v.x = __uint_as_float(r[q * 4 + 0]);
                v.y = __uint_as_float(r[q * 4 + 1]);
                v.z = __uint_as_float(r[q * 4 + 2]);
                v.w = __uint_as_float(r[q * 4 + 3]);
                *(float4*)(orow + ch * 32 + q * 4) = v;
            }
        }
    }
    asm volatile("tcgen05.fence::before_thread_sync;" ::: "memory");
    __syncthreads();
    if (wid == 0) {
        asm volatile("tcgen05.relinquish_alloc_permit.cta_group::1.sync.aligned;");
        asm volatile("tcgen05.dealloc.cta_group::1.sync.aligned.b32 %0, %1;"
                     :: "r"(tmem), "r"(512u));
    }
#else
    // ---- naive fallback (dead code on GB300: sm_103a SASS pass is what executes)
    (void)sb; (void)tiles; (void)wid; (void)lane;
    for (int e = tid; e < BM * BN; e += 256) {
        int r = e / BN, c = e % BN;
        const __half* ar = g_A + (size_t)(m0 + r) * KTOT;
        const __half* wr = g_W + (size_t)(o0 + c) * KTOT;
        float s = 0.f;
        for (int k = 0; k < KTOT; ++k)
            s += __half2float(ar[k]) * __half2float(wr[k]);
        out[(size_t)(m0 + r) * OUTDIM + o0 + c] = s;
    }
#endif
}

// ---------------- launcher ----------------
extern "C" void kernel_launch(void* const* d_in, const int* in_sizes, int n_in,
                              void* d_out, int out_size) {
    (void)in_sizes; (void)n_in; (void)out_size;
    const float* x    = (const float*)d_in[0];
    const float* bw   = (const float*)d_in[1];
    const float* sw   = (const float*)d_in[2];
    const float* grid = (const float*)d_in[3];
    float* out = (float*)d_out;

    {
        int total4 = (OUTDIM * KTOT) / 4;
        wprep_kernel<<<(total4 + 255) / 256, 256>>>(bw, sw);
    }
    {
        int total = BDIM * INDIM;
        aprep_kernel<<<(total + 255) / 256, 256>>>(x, grid);
    }
    cudaFuncSetAttribute(gemm_kernel, cudaFuncAttributeMaxDynamicSharedMemorySize, SMEM_BYTES);
    dim3 g(OUTDIM / BN, BDIM / BM);   // (8, 16) = 128 CTAs, one wave
    gemm_kernel<<<g, 256, SMEM_BYTES>>>(out);
}

// round 16
// speedup vs baseline: 1.0667x; 1.0667x over previous
#include <cuda_runtime.h>
#include <cuda_fp16.h>
#include <cstdint>
#include <cstddef>

// ---------------- problem constants ----------------
#define BDIM   4096
#define INDIM  2048
#define OUTDIM 2048
#define NCOEFF 8
#define KTOT   18432              // INDIM + INDIM*NCOEFF
#define NKT    288                // KTOT / 64

// ---------------- GEMM tiling (R14-proven geometry) ----------------
#define BM 256
#define BN 256
#define BK 64                     // 64 fp16 = 128 B = one SW128 row
#define NSTG 3
#define STG_BYTES   65536         // A 32K (256 rows) + W 32K (256 rows)
#define STG_B_OFF   32768
#define SMEM_BYTES  (2048 + NSTG * STG_BYTES)   // 198656

// ---------------- device scratch: k-tile-major, pre-swizzled ----------------
// g_A layout: [kt][b 0..4095][64 halves], rows of 128B, SW128 baked in.
// g_W layout: [kt][o 0..2047][64 halves].
__device__ __align__(128) __half g_A[(size_t)NKT * BDIM * 64];
__device__ __align__(128) __half g_W[(size_t)NKT * OUTDIM * 64];

// ---------------- arch-feature detection (R10/R13/R14-proven) ----------------
#if defined(__CUDA_ARCH_FEAT_SM103_ALL) || defined(__CUDA_ARCH_FEAT_SM100_ALL) || \
    (defined(__CUDA_ARCH_SPECIFIC__) && defined(__CUDA_ARCH__) && __CUDA_ARCH__ >= 1000)
#define HAS_TC 1
#else
#define HAS_TC 0
#endif

// ---------------- common helpers (baseline-PTX safe) ----------------
__device__ __forceinline__ uint32_t smem_u32(const void* p) {
    uint32_t a;
    asm("{ .reg .u64 t; cvta.to.shared.u64 t, %1; cvt.u32.u64 %0, t; }" : "=r"(a) : "l"(p));
    return a;
}
// swizzled byte offset of element (row r, kc in 0..63) within its 8-row group
__device__ __forceinline__ uint32_t sw_local(int r, int kc) {
    uint32_t local = ((uint32_t)(r & 7) << 7) + ((uint32_t)kc << 1);
    uint32_t chunk = local & ~15u;
    return (chunk ^ ((chunk >> 3) & 0x70)) + (local & 15u);
}

// ---------------- prep: weights -> fp16, k-tile-major swizzled ----------------
__global__ void wprep_kernel(const float* __restrict__ bw, const float* __restrict__ sw) {
    size_t e = ((size_t)blockIdx.x * blockDim.x + threadIdx.x) * 4;
    if (e >= (size_t)OUTDIM * KTOT) return;
    size_t o = e / KTOT;
    size_t k = e - o * KTOT;
    float4 v;
    if (k < INDIM) {
        v = *(const float4*)(bw + o * INDIM + k);
    } else {
        v = *(const float4*)(sw + o * (size_t)(INDIM * NCOEFF) + (k - INDIM));
        v.x = rintf(v.x * 32.f) * 0.03125f;
        v.y = rintf(v.y * 32.f) * 0.03125f;
        v.z = rintf(v.z * 32.f) * 0.03125f;
        v.w = rintf(v.w * 32.f) * 0.03125f;
    }
    __half h[4];
    h[0] = __float2half_rn(v.x); h[1] = __float2half_rn(v.y);
    h[2] = __float2half_rn(v.z); h[3] = __float2half_rn(v.w);
    int kt = (int)(k >> 6), kc = (int)(k & 63);
    size_t group = ((size_t)kt * OUTDIM + ((int)o & ~7)) * 128;
    *(uint2*)((char*)g_W + group + sw_local((int)o, kc)) = *(const uint2*)h;
}

// ---------------- prep: x + cubic b-spline basis -> fp16, k-tile-major swizzled ----------------
__global__ void aprep_kernel(const float* __restrict__ x, const float* __restrict__ grid) {
    int idx = blockIdx.x * blockDim.x + threadIdx.x;
    if (idx >= BDIM * INDIM) return;
    int b = idx / INDIM;
    int i = idx - b * INDIM;
    float xv = x[idx];
    float g[12];
#pragma unroll
    for (int j = 0; j < 12; ++j) g[j] = grid[i * 12 + j];

    float b0[11];
#pragma unroll
    for (int j = 0; j < 11; ++j) b0[j] = (xv >= g[j] && xv < g[j + 1]) ? 1.f : 0.f;
    float b1[10];
#pragma unroll
    for (int j = 0; j < 10; ++j)
        b1[j] = (xv - g[j]) / (g[j + 1] - g[j] + 1e-8f) * b0[j]
              + (g[j + 2] - xv) / (g[j + 2] - g[j + 1] + 1e-8f) * b0[j + 1];
    float b2[9];
#pragma unroll
    for (int j = 0; j < 9; ++j)
        b2[j] = (xv - g[j]) / (g[j + 2] - g[j] + 1e-8f) * b1[j]
              + (g[j + 3] - xv) / (g[j + 3] - g[j + 1] + 1e-8f) * b1[j + 1];
    float b3[8];
#pragma unroll
    for (int j = 0; j < 8; ++j)
        b3[j] = (xv - g[j]) / (g[j + 3] - g[j] + 1e-8f) * b2[j]
              + (g[j + 4] - xv) / (g[j + 4] - g[j + 1] + 1e-8f) * b2[j + 1];

    // x plane: column i
    {
        int kt = i >> 6, kc = i & 63;
        size_t group = ((size_t)kt * BDIM + (b & ~7)) * 128;
        *(__half*)((char*)g_A + group + sw_local(b, kc)) = __float2half_rn(xv);
    }
    // basis: columns 2048 + 8i .. +7 (one 16B chunk, never straddles a k-tile)
    {
        __half h[8];
#pragma unroll
        for (int c = 0; c < 8; ++c) h[c] = __float2half_rn(b3[c]);
        int col0 = INDIM + 8 * i;
        int kt = col0 >> 6, kc = col0 & 63;
        size_t group = ((size_t)kt * BDIM + (b & ~7)) * 128;
        *(uint4*)((char*)g_A + group + sw_local(b, kc)) = *(const uint4*)h;
    }
}

#if HAS_TC
// ================= tcgen05 path helpers (R13/R14-validated) =================
__device__ __forceinline__ void mbar_init(uint32_t a, uint32_t cnt) {
    asm volatile("mbarrier.init.shared.b64 [%0], %1;" :: "r"(a), "r"(cnt) : "memory");
}
__device__ __forceinline__ void mbar_wait(uint32_t a, uint32_t parity) {
    asm volatile(
        "{\n\t.reg .pred P1;\n\t"
        "W_%=:\n\t"
        "mbarrier.try_wait.parity.acquire.cta.shared::cta.b64 P1, [%0], %1, 0x989680;\n\t"
        "@P1 bra.uni D_%=;\n\t"
        "bra.uni W_%=;\n\t"
        "D_%=:\n\t}"
        :: "r"(a), "r"(parity) : "memory");
}
__device__ __forceinline__ void mbar_expect_tx(uint32_t a, uint32_t bytes) {
    asm volatile("mbarrier.arrive.expect_tx.shared.b64 _, [%0], %1;"
                 :: "r"(a), "r"(bytes) : "memory");
}
__device__ __forceinline__ void bulk_ld(uint32_t dst, const void* src, uint32_t bytes,
                                        uint32_t mbar) {
    asm volatile(
        "cp.async.bulk.shared::cluster.global.mbarrier::complete_tx::bytes [%0], [%1], %2, [%3];"
        :: "r"(dst), "l"(src), "r"(bytes), "r"(mbar) : "memory");
}
__device__ __forceinline__ uint64_t mk_desc(uint32_t addr) {
    return ((uint64_t)2 << 61) | ((uint64_t)1 << 46) | ((uint64_t)64 << 32)
         | ((uint64_t)1 << 16) | ((uint64_t)(addr >> 4) & 0x3FFF);
}
#define IDESC 0x08200010u   // F32 accum, f16 x f16, N=128, M=128 (proven)
__device__ __forceinline__ void mma_f16_ss(uint32_t d, uint64_t a, uint64_t b, uint32_t en) {
    asm volatile(
        "{\n\t.reg .pred p;\n\tsetp.ne.u32 p, %4, 0;\n\t"
        "tcgen05.mma.cta_group::1.kind::f16 [%0], %1, %2, %3, {%5,%5,%5,%5}, p;\n\t}"
        :: "r"(d), "l"(a), "l"(b), "r"(IDESC), "r"(en), "r"(0u) : "memory");
}
__device__ __forceinline__ void tmem_ld32(uint32_t* r, uint32_t addr) {
    asm volatile(
        "tcgen05.ld.sync.aligned.32x32b.x32.b32 "
        "{%0, %1, %2, %3, %4, %5, %6, %7, "
        " %8, %9, %10, %11, %12, %13, %14, %15, "
        " %16, %17, %18, %19, %20, %21, %22, %23, "
        " %24, %25, %26, %27, %28, %29, %30, %31}, [%32];"
        : "=r"(r[0]),  "=r"(r[1]),  "=r"(r[2]),  "=r"(r[3]),
          "=r"(r[4]),  "=r"(r[5]),  "=r"(r[6]),  "=r"(r[7]),
          "=r"(r[8]),  "=r"(r[9]),  "=r"(r[10]), "=r"(r[11]),
          "=r"(r[12]), "=r"(r[13]), "=r"(r[14]), "=r"(r[15]),
          "=r"(r[16]), "=r"(r[17]), "=r"(r[18]), "=r"(r[19]),
          "=r"(r[20]), "=r"(r[21]), "=r"(r[22]), "=r"(r[23]),
          "=r"(r[24]), "=r"(r[25]), "=r"(r[26]), "=r"(r[27]),
          "=r"(r[28]), "=r"(r[29]), "=r"(r[30]), "=r"(r[31])
        : "r"(addr));
}
// 16 MMAs for one k-tile stage (R14-verified block)
__device__ __forceinline__ void issue_tile(uint32_t tmem, uint32_t stg, int first) {
    uint64_t da0 = mk_desc(stg);
    uint64_t da1 = mk_desc(stg + 16384);                 // A rows 128..255
    uint64_t db0 = mk_desc(stg + STG_B_OFF);
    uint64_t db1 = mk_desc(stg + STG_B_OFF + 16384);     // W rows 128..255
#pragma unroll
    for (int ks = 0; ks < 4; ++ks) {
        uint64_t d = (uint64_t)(ks * 2);
        uint32_t en = (first && ks == 0) ? 0u : 1u;
        mma_f16_ss(tmem +   0, da0 + d, db0 + d, en);
        mma_f16_ss(tmem + 128, da0 + d, db1 + d, en);
        mma_f16_ss(tmem + 256, da1 + d, db0 + d, en);
        mma_f16_ss(tmem + 384, da1 + d, db1 + d, en);
    }
}
#else
// helper so the baseline fallback reads the swizzled layout correctly
__device__ __forceinline__ float ld_elem(const __half* base, int nrows, int r, int k) {
    int kt = k >> 6, kc = k & 63;
    size_t group = ((size_t)kt * nrows + (r & ~7)) * 128;
    return __half2float(*(const __half*)((const char*)base + group + sw_local(r, kc)));
}
#endif

// ---------------- GEMM: C[4096,2048] = A @ W^T, fp32 accum ----------------
__global__ void __launch_bounds__(256, 1)
gemm_kernel(float* __restrict__ out) {
    extern __shared__ char smem[];
    uint32_t sb = smem_u32(smem);
    uint32_t tiles = (sb + 128 + 1023) & ~1023u;
    int tid = threadIdx.x;
    int wid = tid >> 5;
    int lane = tid & 31;
    int m0 = blockIdx.y * BM;
    int o0 = blockIdx.x * BN;

#if HAS_TC
    // ctrl: [sb] tmem ptr; FULL[s]=sb+8+8s; MMAD[s]=sb+40+8s
    uint32_t FULL = sb + 8, MMAD = sb + 40;
    if (wid == 0)
        asm volatile("tcgen05.alloc.cta_group::1.sync.aligned.shared::cta.b32 [%0], %1;"
                     :: "r"(sb), "r"(512u) : "memory");
    if (tid == 0) {
#pragma unroll
        for (int s = 0; s < NSTG; ++s) {
            mbar_init(FULL + 8u * s, 1);
            mbar_init(MMAD + 8u * s, 1);
        }
    }
    __syncthreads();
    uint32_t tmem;
    asm volatile("ld.shared.b32 %0, [%1];" : "=r"(tmem) : "r"(sb));

    if (tid == 0) {
        const char* baseA = (const char*)g_A;
        const char* baseW = (const char*)g_W;
        uint32_t fph[NSTG] = {0, 0, 0};
        uint32_t mph[NSTG] = {0, 0, 0};
        // prologue: load tiles 0,1
#pragma unroll
        for (int p = 0; p < 2; ++p) {
            uint32_t stg = tiles + (uint32_t)p * STG_BYTES;
            mbar_expect_tx(FULL + 8u * p, STG_BYTES);
            bulk_ld(stg,             baseA + (((size_t)p * BDIM   + m0) << 7), 32768, FULL + 8u * p);
            bulk_ld(stg + STG_B_OFF, baseW + (((size_t)p * OUTDIM + o0) << 7), 32768, FULL + 8u * p);
        }
        for (int kt = 0; kt < NKT; ++kt) {
            int s = kt % NSTG;
            mbar_wait(FULL + 8u * s, fph[s]); fph[s] ^= 1;
            issue_tile(tmem, tiles + (uint32_t)s * STG_BYTES, kt == 0);
            asm volatile(
                "tcgen05.commit.cta_group::1.mbarrier::arrive::one.shared::cluster.b64 [%0];"
                :: "r"(MMAD + 8u * s) : "memory");
            int nx = kt + 2;
            if (nx < NKT) {
                int s2 = nx % NSTG;
                if (nx >= NSTG) { mbar_wait(MMAD + 8u * s2, mph[s2]); mph[s2] ^= 1; }
                uint32_t stg = tiles + (uint32_t)s2 * STG_BYTES;
                mbar_expect_tx(FULL + 8u * s2, STG_BYTES);
                bulk_ld(stg,             baseA + (((size_t)nx * BDIM   + m0) << 7), 32768, FULL + 8u * s2);
                bulk_ld(stg + STG_B_OFF, baseW + (((size_t)nx * OUTDIM + o0) << 7), 32768, FULL + 8u * s2);
            }
        }
        mbar_wait(MMAD + 8u * ((NKT - 1) % NSTG), mph[(NKT - 1) % NSTG]);
    }
    __syncthreads();
    asm volatile("tcgen05.fence::after_thread_sync;" ::: "memory");

    // epilogue (R14-verified): warp w -> m-half h=w>>2, rows (w&3)*32+lane
    {
        int sub = wid & 3;
        int h = wid >> 2;
        float* orow = out + (size_t)(m0 + h * 128 + sub * 32 + lane) * OUTDIM + o0;
        uint32_t cbase = tmem + (uint32_t)(h * 256);
#pragma unroll
        for (int ch = 0; ch < 8; ++ch) {
            uint32_t r[32];
            tmem_ld32(r, cbase + (uint32_t)(ch * 32));
            asm volatile("tcgen05.wait::ld.sync.aligned;" ::: "memory");
#pragma unroll
            for (int q = 0; q < 8; ++q) {
                float4 v;
                v.x = __uint_as_float(r[q * 4 + 0]);
                v.y = __uint_as_float(r[q * 4 + 1]);
                v.z = __uint_as_float(r[q * 4 + 2]);
                v.w = __uint_as_float(r[q * 4 + 3]);
                *(float4*)(orow + ch * 32 + q * 4) = v;
            }
        }
    }
    asm volatile("tcgen05.fence::before_thread_sync;" ::: "memory");
    __syncthreads();
    if (wid == 0) {
        asm volatile("tcgen05.relinquish_alloc_permit.cta_group::1.sync.aligned;");
        asm volatile("tcgen05.dealloc.cta_group::1.sync.aligned.b32 %0, %1;"
                     :: "r"(tmem), "r"(512u));
    }
#else
    // ---- naive fallback (dead code on GB300: the sm_103a pass executes) ----
    (void)sb; (void)tiles; (void)wid; (void)lane;
    for (int e = tid; e < BM * BN; e += 256) {
        int r = e / BN, c = e % BN;
        float s = 0.f;
        for (int k = 0; k < KTOT; ++k)
            s += ld_elem(g_A, BDIM, m0 + r, k) * ld_elem(g_W, OUTDIM, o0 + c, k);
        out[(size_t)(m0 + r) * OUTDIM + o0 + c] = s;
    }
#endif
}

// ---------------- launcher ----------------
extern "C" void kernel_launch(void* const* d_in, const int* in_sizes, int n_in,
                              void* d_out, int out_size) {
    (void)in_sizes; (void)n_in; (void)out_size;
    const float* x    = (const float*)d_in[0];
    const float* bw   = (const float*)d_in[1];
    const float* sw   = (const float*)d_in[2];
    const float* grid = (const float*)d_in[3];
    float* out = (float*)d_out;

    {
        int total4 = (OUTDIM * KTOT) / 4;
        wprep_kernel<<<(total4 + 255) / 256, 256>>>(bw, sw);
    }
    {
        int total = BDIM * INDIM;
        aprep_kernel<<<(total + 255) / 256, 256>>>(x, grid);
    }
    cudaFuncSetAttribute(gemm_kernel, cudaFuncAttributeMaxDynamicSharedMemorySize, SMEM_BYTES);
    dim3 g(OUTDIM / BN, BDIM / BM);   // (8, 16) = 128 CTAs, one wave
    gemm_kernel<<<g, 256, SMEM_BYTES>>>(out);
}

// round 17
// speedup vs baseline: 1.2866x; 1.2062x over previous
#include <cuda_runtime.h>
#include <cuda_fp16.h>
#include <cstdint>
#include <cstddef>

// ---------------- problem constants ----------------
#define BDIM   4096
#define INDIM  2048
#define OUTDIM 2048
#define NCOEFF 8
#define KTOT   18432              // INDIM + INDIM*NCOEFF
#define NKT    288                // KTOT / 64

// ---------------- GEMM tiling: 2-CTA pair covers 256(M) x 512(N) ----------------
#define BMP 256                   // M per cluster pair (128 per CTA)
#define BN  512                   // N per pair (B split: 256 rows per CTA)
#define BK  64                    // 64 fp16 = 128 B = one SW128 row
#define NSTG 4
#define STG_BYTES   49152         // A 16K + B 32K (two 16K n-half blocks)
#define STG_B_OFF   16384
#define SMEM_BYTES  (2048 + NSTG * STG_BYTES)   // 198656

// ---------------- device scratch: k-tile-major, pre-swizzled (R16-proven) ----------------
__device__ __align__(128) __half g_A[(size_t)NKT * BDIM * 64];
__device__ __align__(128) __half g_W[(size_t)NKT * OUTDIM * 64];

// ---------------- arch-feature detection ----------------
#if defined(__CUDA_ARCH_FEAT_SM103_ALL) || defined(__CUDA_ARCH_FEAT_SM100_ALL) || \
    (defined(__CUDA_ARCH_SPECIFIC__) && defined(__CUDA_ARCH__) && __CUDA_ARCH__ >= 1000)
#define HAS_TC 1
#else
#define HAS_TC 0
#endif

// ---------------- common helpers (baseline-PTX safe) ----------------
__device__ __forceinline__ uint32_t smem_u32(const void* p) {
    uint32_t a;
    asm("{ .reg .u64 t; cvta.to.shared.u64 t, %1; cvt.u32.u64 %0, t; }" : "=r"(a) : "l"(p));
    return a;
}
__device__ __forceinline__ uint32_t sw_local(int r, int kc) {
    uint32_t local = ((uint32_t)(r & 7) << 7) + ((uint32_t)kc << 1);
    uint32_t chunk = local & ~15u;
    return (chunk ^ ((chunk >> 3) & 0x70)) + (local & 15u);
}

// ---------------- prep: weights -> fp16, k-tile-major swizzled (R16-proven) ----------------
__global__ void wprep_kernel(const float* __restrict__ bw, const float* __restrict__ sw) {
    size_t e = ((size_t)blockIdx.x * blockDim.x + threadIdx.x) * 4;
    if (e >= (size_t)OUTDIM * KTOT) return;
    size_t o = e / KTOT;
    size_t k = e - o * KTOT;
    float4 v;
    if (k < INDIM) {
        v = *(const float4*)(bw + o * INDIM + k);
    } else {
        v = *(const float4*)(sw + o * (size_t)(INDIM * NCOEFF) + (k - INDIM));
        v.x = rintf(v.x * 32.f) * 0.03125f;
        v.y = rintf(v.y * 32.f) * 0.03125f;
        v.z = rintf(v.z * 32.f) * 0.03125f;
        v.w = rintf(v.w * 32.f) * 0.03125f;
    }
    __half h[4];
    h[0] = __float2half_rn(v.x); h[1] = __float2half_rn(v.y);
    h[2] = __float2half_rn(v.z); h[3] = __float2half_rn(v.w);
    int kt = (int)(k >> 6), kc = (int)(k & 63);
    size_t group = ((size_t)kt * OUTDIM + ((int)o & ~7)) * 128;
    *(uint2*)((char*)g_W + group + sw_local((int)o, kc)) = *(const uint2*)h;
}

// ---------------- prep: x + b-spline basis -> fp16, k-tile-major swizzled (R16-proven) ----------------
__global__ void aprep_kernel(const float* __restrict__ x, const float* __restrict__ grid) {
    int idx = blockIdx.x * blockDim.x + threadIdx.x;
    if (idx >= BDIM * INDIM) return;
    int b = idx / INDIM;
    int i = idx - b * INDIM;
    float xv = x[idx];
    float g[12];
#pragma unroll
    for (int j = 0; j < 12; ++j) g[j] = grid[i * 12 + j];

    float b0[11];
#pragma unroll
    for (int j = 0; j < 11; ++j) b0[j] = (xv >= g[j] && xv < g[j + 1]) ? 1.f : 0.f;
    float b1[10];
#pragma unroll
    for (int j = 0; j < 10; ++j)
        b1[j] = (xv - g[j]) / (g[j + 1] - g[j] + 1e-8f) * b0[j]
              + (g[j + 2] - xv) / (g[j + 2] - g[j + 1] + 1e-8f) * b0[j + 1];
    float b2[9];
#pragma unroll
    for (int j = 0; j < 9; ++j)
        b2[j] = (xv - g[j]) / (g[j + 2] - g[j] + 1e-8f) * b1[j]
              + (g[j + 3] - xv) / (g[j + 3] - g[j + 1] + 1e-8f) * b1[j + 1];
    float b3[8];
#pragma unroll
    for (int j = 0; j < 8; ++j)
        b3[j] = (xv - g[j]) / (g[j + 3] - g[j] + 1e-8f) * b2[j]
              + (g[j + 4] - xv) / (g[j + 4] - g[j + 1] + 1e-8f) * b2[j + 1];

    {
        int kt = i >> 6, kc = i & 63;
        size_t group = ((size_t)kt * BDIM + (b & ~7)) * 128;
        *(__half*)((char*)g_A + group + sw_local(b, kc)) = __float2half_rn(xv);
    }
    {
        __half h[8];
#pragma unroll
        for (int c = 0; c < 8; ++c) h[c] = __float2half_rn(b3[c]);
        int col0 = INDIM + 8 * i;
        int kt = col0 >> 6, kc = col0 & 63;
        size_t group = ((size_t)kt * BDIM + (b & ~7)) * 128;
        *(uint4*)((char*)g_A + group + sw_local(b, kc)) = *(const uint4*)h;
    }
}

#if HAS_TC
// ================= tcgen05 cg2 helpers =================
__device__ __forceinline__ void mbar_init(uint32_t a, uint32_t cnt) {
    asm volatile("mbarrier.init.shared.b64 [%0], %1;" :: "r"(a), "r"(cnt) : "memory");
}
__device__ __forceinline__ void mbar_wait_cta(uint32_t a, uint32_t parity) {
    asm volatile(
        "{\n\t.reg .pred P1;\n\t"
        "W_%=:\n\t"
        "mbarrier.try_wait.parity.acquire.cta.shared::cta.b64 P1, [%0], %1, 0x989680;\n\t"
        "@P1 bra.uni D_%=;\n\t"
        "bra.uni W_%=;\n\t"
        "D_%=:\n\t}"
        :: "r"(a), "r"(parity) : "memory");
}
__device__ __forceinline__ void mbar_wait_cluster(uint32_t a, uint32_t parity) {
    asm volatile(
        "{\n\t.reg .pred P1;\n\t"
        "W_%=:\n\t"
        "mbarrier.try_wait.parity.acquire.cluster.shared::cta.b64 P1, [%0], %1, 0x989680;\n\t"
        "@P1 bra.uni D_%=;\n\t"
        "bra.uni W_%=;\n\t"
        "D_%=:\n\t}"
        :: "r"(a), "r"(parity) : "memory");
}
__device__ __forceinline__ void mbar_expect_tx(uint32_t a, uint32_t bytes) {
    asm volatile("mbarrier.arrive.expect_tx.shared.b64 _, [%0], %1;"
                 :: "r"(a), "r"(bytes) : "memory");
}
__device__ __forceinline__ void bulk_ld(uint32_t dst, const void* src, uint32_t bytes,
                                        uint32_t mbar) {
    asm volatile(
        "cp.async.bulk.shared::cluster.global.mbarrier::complete_tx::bytes [%0], [%1], %2, [%3];"
        :: "r"(dst), "l"(src), "r"(bytes), "r"(mbar) : "memory");
}
// arrive on leader (rank 0) CTA's barrier at same smem offset
__device__ __forceinline__ void arrive_leader(uint32_t local_addr) {
    asm volatile(
        "{\n\t.reg .b32 ra;\n\t"
        "mapa.shared::cluster.u32 ra, %0, 0;\n\t"
        "mbarrier.arrive.shared::cluster.b64 _, [ra];\n\t}"
        :: "r"(local_addr) : "memory");
}
__device__ __forceinline__ uint64_t mk_desc(uint32_t addr) {
    return ((uint64_t)2 << 61) | ((uint64_t)1 << 46) | ((uint64_t)64 << 32)
         | ((uint64_t)1 << 16) | ((uint64_t)(addr >> 4) & 0x3FFF);
}
// cg2 kind::f16: F32 accum(bit4), f16 a/b (0), N=512total? -> per-dispatch N=256: 32<<17; M=256: 16<<24
#define IDESC_CG2 0x10400010u
__device__ __forceinline__ void mma_f16_cg2(uint32_t d, uint64_t a, uint64_t b, uint32_t en) {
    asm volatile(
        "{\n\t.reg .pred p;\n\tsetp.ne.u32 p, %4, 0;\n\t"
        "tcgen05.mma.cta_group::2.kind::f16 [%0], %1, %2, %3, "
        "{%5,%5,%5,%5,%5,%5,%5,%5}, p;\n\t}"
        :: "r"(d), "l"(a), "l"(b), "r"(IDESC_CG2), "r"(en), "r"(0u) : "memory");
}
__device__ __forceinline__ void tmem_ld32(uint32_t* r, uint32_t addr) {
    asm volatile(
        "tcgen05.ld.sync.aligned.32x32b.x32.b32 "
        "{%0, %1, %2, %3, %4, %5, %6, %7, "
        " %8, %9, %10, %11, %12, %13, %14, %15, "
        " %16, %17, %18, %19, %20, %21, %22, %23, "
        " %24, %25, %26, %27, %28, %29, %30, %31}, [%32];"
        : "=r"(r[0]),  "=r"(r[1]),  "=r"(r[2]),  "=r"(r[3]),
          "=r"(r[4]),  "=r"(r[5]),  "=r"(r[6]),  "=r"(r[7]),
          "=r"(r[8]),  "=r"(r[9]),  "=r"(r[10]), "=r"(r[11]),
          "=r"(r[12]), "=r"(r[13]), "=r"(r[14]), "=r"(r[15]),
          "=r"(r[16]), "=r"(r[17]), "=r"(r[18]), "=r"(r[19]),
          "=r"(r[20]), "=r"(r[21]), "=r"(r[22]), "=r"(r[23]),
          "=r"(r[24]), "=r"(r[25]), "=r"(r[26]), "=r"(r[27]),
          "=r"(r[28]), "=r"(r[29]), "=r"(r[30]), "=r"(r[31])
        : "r"(addr));
}
#else
__device__ __forceinline__ float ld_elem(const __half* base, int nrows, int r, int k) {
    int kt = k >> 6, kc = k & 63;
    size_t group = ((size_t)kt * nrows + (r & ~7)) * 128;
    return __half2float(*(const __half*)((const char*)base + group + sw_local(r, kc)));
}
#endif

// ---------------- GEMM: C[4096,2048] = A @ W^T, fp32 accum, 2-CTA clusters ----------------
__global__ void __launch_bounds__(256, 1) __cluster_dims__(2, 1, 1)
gemm_kernel(float* __restrict__ out) {
    extern __shared__ char smem[];
    uint32_t sb = smem_u32(smem);
    uint32_t tiles = (sb + 128 + 1023) & ~1023u;
    int tid = threadIdx.x;
    int wid = tid >> 5;
    int lane = tid & 31;
    int rank = (int)(blockIdx.x & 1);            // == cluster_ctarank for (2,1,1)
    int m0 = blockIdx.y * BMP;                   // pair M origin
    int o0 = (int)(blockIdx.x >> 1) * BN;        // pair N origin

#if HAS_TC
    // ctrl: [sb] tmem ptr; FULL[s]=sb+8+8s; MMAD[s]=sb+40+8s; READY[s]=sb+72+8s
    uint32_t FULL = sb + 8, MMAD = sb + 40, READY = sb + 72;
    if (wid == 0)
        asm volatile("tcgen05.alloc.cta_group::2.sync.aligned.shared::cta.b32 [%0], %1;"
                     :: "r"(sb), "r"(512u) : "memory");
    if (tid == 0) {
#pragma unroll
        for (int s = 0; s < NSTG; ++s) {
            mbar_init(FULL  + 8u * s, 1);
            mbar_init(MMAD  + 8u * s, 1);
            mbar_init(READY + 8u * s, 2);   // both CTAs arrive per stage-use
        }
    }
    __syncthreads();
    asm volatile("barrier.cluster.arrive.aligned;" ::: "memory");
    asm volatile("barrier.cluster.wait.aligned;" ::: "memory");
    uint32_t tmem;
    asm volatile("ld.shared.b32 %0, [%1];" : "=r"(tmem) : "r"(sb));

    if (tid == 0) {
        // ---- loader: bulk-copy stages, gated by slot-free (MMAD) ----
        const char* baseA = (const char*)g_A;
        const char* baseW = (const char*)g_W;
        int arow = m0 + rank * 128;              // this CTA's A half
        int brow0 = o0 + rank * 128;             // n-half 0 rows for this CTA
        int brow1 = o0 + 256 + rank * 128;       // n-half 1 rows
        uint32_t mph[NSTG] = {0, 0, 0, 0};
        for (int kt = 0; kt < NKT; ++kt) {
            int s = kt & (NSTG - 1);
            if (kt >= NSTG) { mbar_wait_cluster(MMAD + 8u * s, mph[s]); mph[s] ^= 1; }
            uint32_t stg = tiles + (uint32_t)s * STG_BYTES;
            mbar_expect_tx(FULL + 8u * s, STG_BYTES);
            bulk_ld(stg, baseA + (((size_t)kt * BDIM + arow) << 7), 16384, FULL + 8u * s);
            bulk_ld(stg + STG_B_OFF,
                    baseW + (((size_t)kt * OUTDIM + brow0) << 7), 16384, FULL + 8u * s);
            bulk_ld(stg + STG_B_OFF + 16384,
                    baseW + (((size_t)kt * OUTDIM + brow1) << 7), 16384, FULL + 8u * s);
        }
        // final completion: commit of last tile (slot 3)
        uint32_t fs = (NKT - 1) & (NSTG - 1);
        mbar_wait_cluster(MMAD + 8u * fs, mph[fs]);
    } else if (tid == 32) {
        // ---- forwarder: local FULL -> leader READY ----
        uint32_t fph[NSTG] = {0, 0, 0, 0};
        for (int kt = 0; kt < NKT; ++kt) {
            int s = kt & (NSTG - 1);
            mbar_wait_cta(FULL + 8u * s, fph[s]); fph[s] ^= 1;
            arrive_leader(READY + 8u * s);
        }
    } else if (tid == 64 && rank == 0) {
        // ---- issuer (leader only): READY -> 8 cg2 MMAs -> multicast commit ----
        uint32_t rph[NSTG] = {0, 0, 0, 0};
        for (int kt = 0; kt < NKT; ++kt) {
            int s = kt & (NSTG - 1);
            mbar_wait_cluster(READY + 8u * s, rph[s]); rph[s] ^= 1;
            uint32_t stg = tiles + (uint32_t)s * STG_BYTES;
            uint64_t da  = mk_desc(stg);
            uint64_t db0 = mk_desc(stg + STG_B_OFF);
            uint64_t db1 = mk_desc(stg + STG_B_OFF + 16384);
#pragma unroll
            for (int ks = 0; ks < 4; ++ks) {
                uint64_t d = (uint64_t)(ks * 2);
                uint32_t en = (kt == 0 && ks == 0) ? 0u : 1u;
                mma_f16_cg2(tmem,       da + d, db0 + d, en);
                mma_f16_cg2(tmem + 256, da + d, db1 + d, en);
            }
            asm volatile(
                "tcgen05.commit.cta_group::2.mbarrier::arrive::one.shared::cluster"
                ".multicast::cluster.b64 [%0], %1;"
                :: "r"(MMAD + 8u * s), "h"((uint16_t)0x3) : "memory");
        }
    }
    __syncthreads();
    asm volatile("tcgen05.fence::after_thread_sync;" ::: "memory");

    // epilogue: warp w -> rows (w&3)*32+lane of this CTA's 128, n-half h=w>>2
    {
        int sub = wid & 3;
        int h = wid >> 2;
        float* orow = out + (size_t)(m0 + rank * 128 + sub * 32 + lane) * OUTDIM
                          + o0 + h * 256;
        uint32_t cbase = tmem + (uint32_t)(h * 256);
#pragma unroll
        for (int ch = 0; ch < 8; ++ch) {
            uint32_t r[32];
            tmem_ld32(r, cbase + (uint32_t)(ch * 32));
            asm volatile("tcgen05.wait::ld.sync.aligned;" ::: "memory");
#pragma unroll
            for (int q = 0; q < 8; ++q) {
                float4 v;
                v.x = __uint_as_float(r[q * 4 + 0]);
                v.y = __uint_as_float(r[q * 4 + 1]);
                v.z = __uint_as_float(r[q * 4 + 2]);
                v.w = __uint_as_float(r[q * 4 + 3]);
                *(float4*)(orow + ch * 32 + q * 4) = v;
            }
        }
    }
    asm volatile("tcgen05.fence::before_thread_sync;" ::: "memory");
    __syncthreads();
    if (wid == 0) {
        asm volatile("tcgen05.relinquish_alloc_permit.cta_group::2.sync.aligned;");
        asm volatile("tcgen05.dealloc.cta_group::2.sync.aligned.b32 %0, %1;"
                     :: "r"(tmem), "r"(512u));
    }
    asm volatile("barrier.cluster.arrive.aligned;" ::: "memory");
    asm volatile("barrier.cluster.wait.aligned;" ::: "memory");
#else
    // ---- naive fallback (dead code on GB300: sm_103a pass executes) ----
    (void)sb; (void)tiles; (void)wid; (void)lane;
    for (int e = tid; e < 128 * BN; e += 256) {
        int r = e / BN, c = e % BN;
        int row = m0 + rank * 128 + r;
        float s = 0.f;
        for (int k = 0; k < KTOT; ++k)
            s += ld_elem(g_A, BDIM, row, k) * ld_elem(g_W, OUTDIM, o0 + c, k);
        out[(size_t)row * OUTDIM + o0 + c] = s;
    }
#endif
}

// ---------------- launcher ----------------
extern "C" void kernel_launch(void* const* d_in, const int* in_sizes, int n_in,
                              void* d_out, int out_size) {
    (void)in_sizes; (void)n_in; (void)out_size;
    const float* x    = (const float*)d_in[0];
    const float* bw   = (const float*)d_in[1];
    const float* sw   = (const float*)d_in[2];
    const float* grid = (const float*)d_in[3];
    float* out = (float*)d_out;

    {
        int total4 = (OUTDIM * KTOT) / 4;
        wprep_kernel<<<(total4 + 255) / 256, 256>>>(bw, sw);
    }
    {
        int total = BDIM * INDIM;
        aprep_kernel<<<(total + 255) / 256, 256>>>(x, grid);
    }
    cudaFuncSetAttribute(gemm_kernel, cudaFuncAttributeMaxDynamicSharedMemorySize, SMEM_BYTES);
    dim3 g(2 * (OUTDIM / BN), BDIM / BMP);   // (8, 16) = 128 CTAs = 64 clusters
    gemm_kernel<<<g, 256, SMEM_BYTES>>>(out);
}